// round 13
// baseline (speedup 1.0000x reference)
#include <cuda_runtime.h>
#include <cuda_bf16.h>
#include <math.h>

#define NA 8192
#define NB 32
#define NK 128
#define ND 128

__device__ float g_c[NA * NK];
__device__ float g_s[NA * NK];
__device__ float g_F[NB * NK * ND];
__device__ float g_FSre[NB * NK * ND];
__device__ float g_FSim[NB * NK * ND];
__device__ int   g_seg[NB + 1];

struct DevPtrs {
    const void *kv, *pos, *h, *W1, *b1, *W2, *b2, *W3, *b3, *batch;
    int isbf16;
    int batch64;
};
__device__ DevPtrs g_P;

__device__ __forceinline__ float ldf(const void* p, long i, int isbf) {
    if (isbf) return __bfloat162float(((const __nv_bfloat16*)p)[i]);
    return ((const float*)p)[i];
}
__device__ __forceinline__ int ldb(const void* p, int i, int b64) {
    if (b64) return (int)(((const long long*)p)[i]);
    return ((const int*)p)[i];
}
__device__ __forceinline__ float gelu_t(float x) {
    float x3 = x * x * x;
    return 0.5f * x * (1.0f + tanhf(0.7978845608028654f * fmaf(0.044715f, x3, x)));
}
__device__ static bool is_b32(const int* w) {
    int prev = -1;
    for (int j = 0; j < 128; j++) {
        int v = w[j];
        if (v < 0 || v > 63 || v < prev) return false;
        prev = v;
    }
    return true;
}
__device__ static bool is_b64(const int* w) {
    int prev = -1;
    for (int j = 0; j < 64; j++) {
        int lo = w[2*j], hi = w[2*j+1];
        if (hi != 0 || lo < 0 || lo > 63 || lo < prev) return false;
        prev = lo;
    }
    return true;
}

__global__ void setup_kernel(const void* kv, const void* pos, const void* h,
                             const void* W1, const void* b1, const void* b2,
                             const void* b3, const void* c0, const void* c1,
                             const void* c2, const void* batch_direct, int mf) {
    int tid = threadIdx.x;
    if (tid == 0) {
        DevPtrs P;
        P.kv = kv; P.pos = pos; P.h = h; P.W1 = W1;
        P.b1 = b1; P.b2 = b2; P.b3 = b3;
        const void* batch = batch_direct;
        const void* w2 = c0; const void* w3 = c1;
        if (!batch) {
            const void* cand[3] = {c0, c1, c2};
            int bi = -1;
            for (int i = 0; i < 3; i++) {
                const int* w = (const int*)cand[i];
                if (is_b32(w) || is_b64(w)) { bi = i; break; }
            }
            if (bi < 0) bi = 2;
            int nw = 0; const void* ws[2] = {0, 0};
            for (int i = 0; i < 3; i++) if (i != bi) ws[nw++] = cand[i];
            w2 = ws[0]; w3 = ws[1]; batch = cand[bi];
        }
        P.W2 = w2; P.W3 = w3; P.batch = batch;
        const int* bw = (const int*)batch;
        P.batch64 = (is_b64(bw) && !is_b32(bw)) ? 1 : 0;
        if (mf == 2) P.isbf16 = 1;
        else if (mf == 4) P.isbf16 = 0;
        else {
            const unsigned short* p16 = (const unsigned short*)pos;
            int hits = 0;
            for (int i = 0; i < 256; i++) {
                int e = (p16[i] >> 7) & 0xFF;
                if (e >= 110 && e <= 135) hits++;
            }
            P.isbf16 = (hits > 205);
        }
        g_P = P;
    }
    __syncthreads();
    if (tid <= NB) {
        const void* batch = g_P.batch;
        int b64 = g_P.batch64;
        int lo = 0, hi = NA;
        while (lo < hi) {
            int m = (lo + hi) >> 1;
            if (ldb(batch, m, b64) < tid) lo = m + 1; else hi = m;
        }
        if (lo < 0) lo = 0;
        if (lo > NA) lo = NA;
        g_seg[tid] = lo;
    }
}

__global__ void zero_kernel(unsigned int* out, long words) {
    long i = blockIdx.x * (long)blockDim.x + threadIdx.x;
    if (i < words) out[i] = 0u;
}

// ---------------------------------------------------------------------------
// theta: 2 atoms per block, 256 threads, MUFU sincos
// ---------------------------------------------------------------------------
__global__ void __launch_bounds__(256) theta_kernel() {
    const DevPtrs P = g_P;
    int n0 = blockIdx.x * 2;
    int tid = threadIdx.x;
    int a = tid >> 7;
    int k = tid & 127;
    __shared__ float p[2][3];
    __shared__ int bsh[2];
    if (tid < 6) p[tid / 3][tid % 3] = ldf(P.pos, (long)n0 * 3 + tid, P.isbf16);
    if (tid < 2) bsh[tid] = ldb(P.batch, n0 + tid, P.batch64) & 31;
    __syncthreads();
    int n = n0 + a;
    long base = ((long)bsh[a] * NK + k) * 3;
    float th = fmaf(p[a][0], ldf(P.kv, base, P.isbf16),
               fmaf(p[a][1], ldf(P.kv, base + 1, P.isbf16),
                    p[a][2] * ldf(P.kv, base + 2, P.isbf16)));
    float sv, cv;
    __sincosf(th, &sv, &cv);
    g_c[n * NK + k] = cv;
    g_s[n * NK + k] = sv;
}

// ---------------------------------------------------------------------------
// MLP v4: 8 rows/block, 512 blocks, 256 threads (2 row-groups x 4 rows),
// j-loop unrolled x8 so 8 weight LDGs batch in flight.
// ---------------------------------------------------------------------------
#define MROWS 8
__global__ void __launch_bounds__(256) mlp_kernel() {
    __shared__ float a1[MROWS][NK];
    __shared__ float a2[MROWS][NK];
    __shared__ float kvs[MROWS * 3];

    const DevPtrs P = g_P;
    int isbf = P.isbf16;
    int row0 = blockIdx.x * MROWS;
    int tid = threadIdx.x;
    int t = tid & 127;
    int g = tid >> 7;                 // row group: rows g*4 .. g*4+3

    if (tid < MROWS * 3) kvs[tid] = ldf(P.kv, (long)row0 * 3 + tid, isbf);

    float w10 = ldf(P.W1, t, isbf);
    float w11 = ldf(P.W1, NK + t, isbf);
    float w12 = ldf(P.W1, 2 * NK + t, isbf);
    float bv1 = ldf(P.b1, t, isbf);
    __syncthreads();
#pragma unroll
    for (int r = 0; r < 4; r++) {
        int row = g * 4 + r;
        float x = fmaf(kvs[row*3], w10, fmaf(kvs[row*3+1], w11,
                  fmaf(kvs[row*3+2], w12, bv1)));
        a1[row][t] = gelu_t(x);
    }
    __syncthreads();

    // layer 2
    {
        float y[4];
        float bv = ldf(P.b2, t, isbf);
#pragma unroll
        for (int r = 0; r < 4; r++) y[r] = bv;
        for (int j = 0; j < NK; j += 8) {
            float w0 = ldf(P.W2, (long)j * NK + t, isbf);
            float w1 = ldf(P.W2, (long)(j+1) * NK + t, isbf);
            float w2 = ldf(P.W2, (long)(j+2) * NK + t, isbf);
            float w3 = ldf(P.W2, (long)(j+3) * NK + t, isbf);
            float w4 = ldf(P.W2, (long)(j+4) * NK + t, isbf);
            float w5 = ldf(P.W2, (long)(j+5) * NK + t, isbf);
            float w6 = ldf(P.W2, (long)(j+6) * NK + t, isbf);
            float w7 = ldf(P.W2, (long)(j+7) * NK + t, isbf);
#pragma unroll
            for (int r = 0; r < 4; r++) {
                float4 aL = *(const float4*)&a1[g*4 + r][j];
                float4 aH = *(const float4*)&a1[g*4 + r][j+4];
                y[r] = fmaf(aL.x, w0, y[r]);
                y[r] = fmaf(aL.y, w1, y[r]);
                y[r] = fmaf(aL.z, w2, y[r]);
                y[r] = fmaf(aL.w, w3, y[r]);
                y[r] = fmaf(aH.x, w4, y[r]);
                y[r] = fmaf(aH.y, w5, y[r]);
                y[r] = fmaf(aH.z, w6, y[r]);
                y[r] = fmaf(aH.w, w7, y[r]);
            }
        }
#pragma unroll
        for (int r = 0; r < 4; r++) a2[g*4 + r][t] = gelu_t(y[r]);
    }
    __syncthreads();

    // layer 3
    {
        float y[4];
        float bv = ldf(P.b3, t, isbf);
#pragma unroll
        for (int r = 0; r < 4; r++) y[r] = bv;
        for (int j = 0; j < NK; j += 8) {
            float w0 = ldf(P.W3, (long)j * NK + t, isbf);
            float w1 = ldf(P.W3, (long)(j+1) * NK + t, isbf);
            float w2 = ldf(P.W3, (long)(j+2) * NK + t, isbf);
            float w3 = ldf(P.W3, (long)(j+3) * NK + t, isbf);
            float w4 = ldf(P.W3, (long)(j+4) * NK + t, isbf);
            float w5 = ldf(P.W3, (long)(j+5) * NK + t, isbf);
            float w6 = ldf(P.W3, (long)(j+6) * NK + t, isbf);
            float w7 = ldf(P.W3, (long)(j+7) * NK + t, isbf);
#pragma unroll
            for (int r = 0; r < 4; r++) {
                float4 aL = *(const float4*)&a2[g*4 + r][j];
                float4 aH = *(const float4*)&a2[g*4 + r][j+4];
                y[r] = fmaf(aL.x, w0, y[r]);
                y[r] = fmaf(aL.y, w1, y[r]);
                y[r] = fmaf(aL.z, w2, y[r]);
                y[r] = fmaf(aL.w, w3, y[r]);
                y[r] = fmaf(aH.x, w4, y[r]);
                y[r] = fmaf(aH.y, w5, y[r]);
                y[r] = fmaf(aH.z, w6, y[r]);
                y[r] = fmaf(aH.w, w7, y[r]);
            }
        }
#pragma unroll
        for (int r = 0; r < 4; r++)
            g_F[(long)(row0 + g*4 + r) * NK + t] = y[r];
    }
}

// ---------------------------------------------------------------------------
// segsum: grid (NB, 4), 512 threads, thread owns 4d x 2k (32 k per block)
// ---------------------------------------------------------------------------
__global__ void __launch_bounds__(512) segsum_kernel() {
    const DevPtrs P = g_P;
    int isbf = P.isbf16;
    int b = blockIdx.x;
    int k0 = blockIdx.y * 32;
    int tid = threadIdx.x;
    int d0 = (tid & 31) * 4;
    int kq = tid >> 5;
    int s0 = g_seg[b], s1 = g_seg[b + 1];
    if (s1 < s0) s1 = s0;

    __shared__ float csh[32][32], ssh[32][32];
    __shared__ float hsh[32][ND];

    float aR[2][4], aI[2][4];
#pragma unroll
    for (int j = 0; j < 2; j++)
#pragma unroll
        for (int i = 0; i < 4; i++) { aR[j][i] = 0.f; aI[j][i] = 0.f; }

    for (int n0 = s0; n0 < s1; n0 += 32) {
        int cnt = min(32, s1 - n0);
        for (int i = tid; i < cnt * 32; i += 512) {
            int a = i >> 5, kk = i & 31;
            csh[a][kk] = g_c[(n0 + a) * NK + k0 + kk];
            ssh[a][kk] = g_s[(n0 + a) * NK + k0 + kk];
        }
        if (isbf) {
            for (int i = tid; i < cnt * ND; i += 512) {
                int a = i >> 7, d = i & 127;
                hsh[a][d] = __bfloat162float(((const __nv_bfloat16*)P.h)[(long)(n0 + a) * ND + d]);
            }
        } else {
            const float4* h4 = (const float4*)P.h;
            for (int i = tid; i < cnt * 32; i += 512) {
                int a = i >> 5, dq = i & 31;
                ((float4*)&hsh[a][0])[dq] = h4[(long)(n0 + a) * 32 + dq];
            }
        }
        __syncthreads();
#pragma unroll 2
        for (int a = 0; a < cnt; a++) {
            float4 hv = *(const float4*)&hsh[a][d0];
            float c0v = csh[a][kq*2],     s0v = ssh[a][kq*2];
            float c1v = csh[a][kq*2 + 1], s1v = ssh[a][kq*2 + 1];
            aR[0][0] = fmaf(c0v, hv.x, aR[0][0]); aI[0][0] = fmaf(-s0v, hv.x, aI[0][0]);
            aR[0][1] = fmaf(c0v, hv.y, aR[0][1]); aI[0][1] = fmaf(-s0v, hv.y, aI[0][1]);
            aR[0][2] = fmaf(c0v, hv.z, aR[0][2]); aI[0][2] = fmaf(-s0v, hv.z, aI[0][2]);
            aR[0][3] = fmaf(c0v, hv.w, aR[0][3]); aI[0][3] = fmaf(-s0v, hv.w, aI[0][3]);
            aR[1][0] = fmaf(c1v, hv.x, aR[1][0]); aI[1][0] = fmaf(-s1v, hv.x, aI[1][0]);
            aR[1][1] = fmaf(c1v, hv.y, aR[1][1]); aI[1][1] = fmaf(-s1v, hv.y, aI[1][1]);
            aR[1][2] = fmaf(c1v, hv.z, aR[1][2]); aI[1][2] = fmaf(-s1v, hv.z, aI[1][2]);
            aR[1][3] = fmaf(c1v, hv.w, aR[1][3]); aI[1][3] = fmaf(-s1v, hv.w, aI[1][3]);
        }
        __syncthreads();
    }
#pragma unroll
    for (int j = 0; j < 2; j++) {
        long off = ((long)b * NK + k0 + kq*2 + j) * ND + d0;
        float4 f = *(const float4*)&g_F[off];
        float4 vR = make_float4(f.x * aR[j][0], f.y * aR[j][1],
                                f.z * aR[j][2], f.w * aR[j][3]);
        float4 vI = make_float4(f.x * aI[j][0], f.y * aI[j][1],
                                f.z * aI[j][2], f.w * aI[j][3]);
        *(float4*)&g_FSre[off] = vR;
        *(float4*)&g_FSim[off] = vI;
    }
}

// ---------------------------------------------------------------------------
// out: grid (NB, 8), 256 threads, 32-atom tiles, thread owns 4a x 4d.
// mode 0 = real fp32 | 1 = fp32 pairs | 2 = bf16 pairs
// ---------------------------------------------------------------------------
__global__ void __launch_bounds__(256) out_kernel(void* __restrict__ outp,
                                                  int mode, long cap) {
    int b = blockIdx.x;
    int s0 = g_seg[b], s1 = g_seg[b + 1];
    if (s1 < s0) s1 = s0;
    int tid = threadIdx.x;
    int d0 = (tid & 31) * 4;
    int a0 = (tid >> 5) * 4;

    __shared__ float csh[32][NK], ssh[32][NK];

    const float4* FR4 = (const float4*)(g_FSre + (long)b * NK * ND);
    const float4* FI4 = (const float4*)(g_FSim + (long)b * NK * ND);
    int dq = d0 >> 2;

    for (int n0 = s0 + blockIdx.y * 32; n0 < s1; n0 += 8 * 32) {
        int cnt = min(32, s1 - n0);
        for (int i = tid; i < cnt * 32; i += 256) {
            int a = i >> 5, kk = i & 31;
            ((float4*)&csh[a][0])[kk] = *(const float4*)&g_c[(n0 + a) * NK + kk*4];
            ((float4*)&ssh[a][0])[kk] = *(const float4*)&g_s[(n0 + a) * NK + kk*4];
        }
        __syncthreads();

        if (mode == 0) {
            float oR[4][4];
#pragma unroll
            for (int u = 0; u < 4; u++)
#pragma unroll
                for (int i = 0; i < 4; i++) oR[u][i] = 0.f;
#pragma unroll 2
            for (int k = 0; k < NK; k++) {
                float4 fr = FR4[k * 32 + dq];
                float4 fi = FI4[k * 32 + dq];
#pragma unroll
                for (int u = 0; u < 4; u++) {
                    float c = csh[a0 + u][k];
                    float s = ssh[a0 + u][k];
                    oR[u][0] = fmaf(c, fr.x, fmaf(-s, fi.x, oR[u][0]));
                    oR[u][1] = fmaf(c, fr.y, fmaf(-s, fi.y, oR[u][1]));
                    oR[u][2] = fmaf(c, fr.z, fmaf(-s, fi.z, oR[u][2]));
                    oR[u][3] = fmaf(c, fr.w, fmaf(-s, fi.w, oR[u][3]));
                }
            }
#pragma unroll
            for (int u = 0; u < 4; u++) {
                int a = a0 + u;
                if (a < cnt) {
                    long idx = (long)(n0 + a) * ND + d0;
                    if (idx + 4 <= cap)
                        *(float4*)((float*)outp + idx) =
                            make_float4(oR[u][0], oR[u][1], oR[u][2], oR[u][3]);
                }
            }
        } else {
            float oR[4][4], oI[4][4];
#pragma unroll
            for (int u = 0; u < 4; u++)
#pragma unroll
                for (int i = 0; i < 4; i++) { oR[u][i] = 0.f; oI[u][i] = 0.f; }
            for (int k = 0; k < NK; k++) {
                float4 fr = FR4[k * 32 + dq];
                float4 fi = FI4[k * 32 + dq];
#pragma unroll
                for (int u = 0; u < 4; u++) {
                    float c = csh[a0 + u][k];
                    float s = ssh[a0 + u][k];
                    oR[u][0] = fmaf(c, fr.x, fmaf(-s, fi.x, oR[u][0]));
                    oR[u][1] = fmaf(c, fr.y, fmaf(-s, fi.y, oR[u][1]));
                    oR[u][2] = fmaf(c, fr.z, fmaf(-s, fi.z, oR[u][2]));
                    oR[u][3] = fmaf(c, fr.w, fmaf(-s, fi.w, oR[u][3]));
                    oI[u][0] = fmaf(s, fr.x, fmaf(c, fi.x, oI[u][0]));
                    oI[u][1] = fmaf(s, fr.y, fmaf(c, fi.y, oI[u][1]));
                    oI[u][2] = fmaf(s, fr.z, fmaf(c, fi.z, oI[u][2]));
                    oI[u][3] = fmaf(s, fr.w, fmaf(c, fi.w, oI[u][3]));
                }
            }
            for (int u = 0; u < 4; u++) {
                int a = a0 + u;
                if (a < cnt) {
                    long row = (long)(n0 + a) * ND;
                    for (int i = 0; i < 4; i++) {
                        long idx = row + d0 + i;
                        if (mode == 1) {
                            if (2 * idx + 1 < cap)
                                ((float2*)outp)[idx] = make_float2(oR[u][i], oI[u][i]);
                        } else {
                            if (idx + 1 <= cap) {
                                __nv_bfloat162 v;
                                v.x = __float2bfloat16(oR[u][i]);
                                v.y = __float2bfloat16(oI[u][i]);
                                ((__nv_bfloat162*)outp)[idx] = v;
                            }
                        }
                    }
                }
            }
        }
        __syncthreads();
    }
}

// ---------------------------------------------------------------------------
extern "C" void kernel_launch(void* const* d_in, const int* in_sizes, int n_in,
                              void* d_out, int out_size) {
    long mx = 0;
    for (int i = 0; i < n_in; i++) if ((long)in_sizes[i] > mx) mx = in_sizes[i];
    long mf;
    if (mx == 1048576L) mf = 1;
    else if (mx == 2097152L) mf = 2;
    else if (mx == 4194304L) mf = 4;
    else return;

    const void *kv = 0, *pos = 0, *h = 0, *W1 = 0;
    const void* bias[3] = {0, 0, 0};
    const void* grp[3] = {0, 0, 0};
    const void* extra = 0;
    int nb = 0, ng = 0;
    long extra_sz = (mf == 1) ? 8192 : (mf == 2) ? 65536 : 32768;
    for (int i = 0; i < n_in; i++) {
        long s = in_sizes[i];
        const void* p = d_in[i];
        if (s == 12288L * mf)        kv = p;
        else if (s == 24576L * mf)   pos = p;
        else if (s == 1048576L * mf) h = p;
        else if (s == 384L * mf)     W1 = p;
        else if (s == 128L * mf)   { if (nb < 3) bias[nb++] = p; }
        else if (s == 16384L * mf) { if (ng < 3) grp[ng++] = p; }
        else if (s == extra_sz)      extra = p;
    }
    if (!kv || !pos || !h || !W1 || nb < 3) return;

    const void *c0 = 0, *c1 = 0, *c2 = 0, *bd = 0;
    if (ng == 3)               { c0 = grp[0]; c1 = grp[1]; c2 = grp[2]; }
    else if (ng == 2 && extra) { c0 = grp[0]; c1 = grp[1]; bd = extra; }
    else return;

    int mode; long cap;
    if (out_size == 1048576)      { mode = 0; cap = 1048576L; }
    else if (out_size == 2097152) { mode = 1; cap = 2097152L; }
    else if (out_size == 8388608) { mode = 1; cap = 2097152L; }
    else if (out_size == 4194304) { mode = 2; cap = 1048576L; }
    else                          { mode = 0; cap = (long)out_size / 4; }

    // mode 0 writes every output element (segments partition [0, NA)) — no
    // pre-zero needed. Other modes may leave gaps; keep the zero fill there.
    if (mode != 0) {
        long words = (long)out_size / 4;
        if (words > 0)
            zero_kernel<<<(int)((words + 255) / 256), 256>>>((unsigned int*)d_out, words);
    }

    setup_kernel<<<1, 64>>>(kv, pos, h, W1, bias[0], bias[1], bias[2],
                            c0, c1, c2, bd, (int)mf);
    theta_kernel<<<NA / 2, 256>>>();
    mlp_kernel<<<NB * NK / MROWS, 256>>>();
    segsum_kernel<<<dim3(NB, 4), 512>>>();
    out_kernel<<<dim3(NB, 8), 256>>>(d_out, mode, cap);
}